// round 2
// baseline (speedup 1.0000x reference)
#include <cuda_runtime.h>

// ---------------- constants ----------------
#define NN      50000
#define MAXE    2000000
#define HEADS   4
#define HID     64
#define HC      256          // HEADS*HID
#define OUTC    128

// ---------------- device scratch ----------------
__device__ float    g_proj[(size_t)NN * HC];
__device__ float    g_acc [(size_t)NN * HC];
__device__ float    g_h0  [(size_t)NN * HC];
__device__ float    g_h1  [(size_t)NN * HC];
__device__ float    g_lin [(size_t)NN * OUTC];
__device__ float    g_als [NN * HEADS];
__device__ float    g_ald [NN * HEADS];
__device__ unsigned g_mu  [NN * HEADS];
__device__ float    g_sden[NN * HEADS];
__device__ int      g_src [MAXE];
__device__ int      g_dst [MAXE];
__device__ int      g_is64;

// ---------------- helpers ----------------
__device__ __forceinline__ unsigned encf(float f) {
    unsigned u = __float_as_uint(f);
    return (u & 0x80000000u) ? ~u : (u | 0x80000000u);
}
__device__ __forceinline__ float decf(unsigned u) {
    return (u & 0x80000000u) ? __uint_as_float(u & 0x7fffffffu)
                             : __uint_as_float(~u);
}
__device__ __forceinline__ float lrelu(float v) { return v > 0.f ? v : 0.2f * v; }

__device__ __forceinline__ void red4(float* addr, float a, float b, float c, float d) {
    asm volatile("red.global.add.v4.f32 [%0], {%1,%2,%3,%4};"
                 :: "l"(addr), "f"(a), "f"(b), "f"(c), "f"(d) : "memory");
}

// ---------------- edge index normalization ----------------
__global__ void probe_kernel(const int* p32, int nchk) {
    if (blockIdx.x == 0 && threadIdx.x == 0) {
        int z = 0;
        for (int k = 0; k < nchk; k++)
            if (p32[2 * k + 1] == 0) z++;
        g_is64 = (z * 2 > nchk) ? 1 : 0;
    }
}

__global__ void convert_kernel(const void* ei, int E) {
    int e = blockIdx.x * blockDim.x + threadIdx.x;
    if (e >= E || e >= MAXE) return;
    if (g_is64) {
        const long long* p = (const long long*)ei;
        g_src[e] = (int)p[e];
        g_dst[e] = (int)p[(size_t)E + e];
    } else {
        const int* p = (const int*)ei;
        g_src[e] = p[e];
        g_dst[e] = p[E + e];
    }
}

// ---------------- GEMM: C[M,N] = A[M,K] @ B[K,N], fp32, row-major ----------------
// BM=BN=64, BK=16, 256 threads, 4x4 register microtile
__global__ void gemm64(const float* __restrict__ A, const float* __restrict__ B,
                       float* __restrict__ C, int M, int K, int Nn) {
    __shared__ float As[16][68];
    __shared__ float Bs[16][68];
    const int tid = threadIdx.x;
    const int tx = tid & 15;
    const int ty = tid >> 4;
    const int rowBase = blockIdx.y * 64;
    const int colBase = blockIdx.x * 64;

    const int aRow = tid >> 2;           // 0..63
    const int aCol = (tid & 3) * 4;      // 0,4,8,12
    const int bRow = tid >> 4;           // 0..15
    const int bCol = (tid & 15) * 4;     // 0..60

    float acc[4][4];
#pragma unroll
    for (int i = 0; i < 4; i++)
#pragma unroll
        for (int j = 0; j < 4; j++) acc[i][j] = 0.f;

    for (int k0 = 0; k0 < K; k0 += 16) {
        float4 av = make_float4(0.f, 0.f, 0.f, 0.f);
        int gr = rowBase + aRow;
        if (gr < M) av = *(const float4*)(A + (size_t)gr * K + k0 + aCol);
        As[aCol + 0][aRow] = av.x;
        As[aCol + 1][aRow] = av.y;
        As[aCol + 2][aRow] = av.z;
        As[aCol + 3][aRow] = av.w;
        float4 bv = *(const float4*)(B + (size_t)(k0 + bRow) * Nn + colBase + bCol);
        *(float4*)&Bs[bRow][bCol] = bv;
        __syncthreads();
#pragma unroll
        for (int kk = 0; kk < 16; kk++) {
            float4 a4 = *(const float4*)&As[kk][ty * 4];
            float4 b4 = *(const float4*)&Bs[kk][tx * 4];
            float a[4] = {a4.x, a4.y, a4.z, a4.w};
            float b[4] = {b4.x, b4.y, b4.z, b4.w};
#pragma unroll
            for (int i = 0; i < 4; i++)
#pragma unroll
                for (int j = 0; j < 4; j++) acc[i][j] = fmaf(a[i], b[j], acc[i][j]);
        }
        __syncthreads();
    }
#pragma unroll
    for (int i = 0; i < 4; i++) {
        int r = rowBase + ty * 4 + i;
        if (r < M) {
            float4 v = make_float4(acc[i][0], acc[i][1], acc[i][2], acc[i][3]);
            *(float4*)(C + (size_t)r * Nn + colBase + tx * 4) = v;
        }
    }
}

// ---------------- per-node attention logits ----------------
template <int H, int C>
__global__ void logits_kernel(const float* __restrict__ proj,
                              const float* __restrict__ a_s,
                              const float* __restrict__ a_d,
                              float* __restrict__ als, float* __restrict__ ald) {
    int w = (blockIdx.x * blockDim.x + threadIdx.x) >> 5;
    int lane = threadIdx.x & 31;
    if (w >= NN * H) return;
    int n = w / H, h = w % H;
    const float* p = proj + (size_t)n * H * C + h * C;
    float ss = 0.f, sd = 0.f;
#pragma unroll
    for (int c = lane; c < C; c += 32) {
        float v = p[c];
        ss = fmaf(v, a_s[h * C + c], ss);
        sd = fmaf(v, a_d[h * C + c], sd);
    }
#pragma unroll
    for (int o = 16; o > 0; o >>= 1) {
        ss += __shfl_xor_sync(0xffffffffu, ss, o);
        sd += __shfl_xor_sync(0xffffffffu, sd, o);
    }
    if (lane == 0) {
        als[n * H + h] = ss;
        ald[n * H + h] = sd;
    }
}

// ---------------- self-loop init of max ----------------
__global__ void self_init(const float* __restrict__ als, const float* __restrict__ ald,
                          unsigned* __restrict__ mu, int total) {
    int i = blockIdx.x * blockDim.x + threadIdx.x;
    if (i >= total) return;
    mu[i] = encf(lrelu(als[i] + ald[i]));
}

// ---------------- edge max pass ----------------
template <int H>
__global__ void edge_max(const int* __restrict__ src, const int* __restrict__ dst,
                         const float* __restrict__ als, const float* __restrict__ ald,
                         unsigned* __restrict__ mu, int E) {
    int e = blockIdx.x * blockDim.x + threadIdx.x;
    if (e >= E) return;
    int s = src[e], d = dst[e];
#pragma unroll
    for (int h = 0; h < H; h++) {
        float v = lrelu(als[s * H + h] + ald[d * H + h]);
        atomicMax(&mu[d * H + h], encf(v));
    }
}

// ---------------- self-loop init of accumulators ----------------
__global__ void agg_init(const float* __restrict__ proj, const float* __restrict__ als,
                         const float* __restrict__ ald, const unsigned* __restrict__ mu,
                         float* __restrict__ acc, float* __restrict__ sden,
                         int HCl, int Cshift, int H) {
    int idx = blockIdx.x * blockDim.x + threadIdx.x;
    int Q = HCl >> 2;
    if (idx >= NN * Q) return;
    int n = idx / Q;
    int c = (idx - n * Q) * 4;
    int h = c >> Cshift;
    float v = lrelu(als[n * H + h] + ald[n * H + h]);
    float w = __expf(v - decf(mu[n * H + h]));
    if ((c & ((1 << Cshift) - 1)) == 0) sden[n * H + h] = w;
    float4 p = *(const float4*)(proj + (size_t)n * HCl + c);
    float4 o = make_float4(w * p.x, w * p.y, w * p.z, w * p.w);
    *(float4*)(acc + (size_t)n * HCl + c) = o;
}

// ---------------- edge aggregation: warp per edge ----------------
// HC=256 (4 heads x 64): each lane covers 8 channels (2 x float4)
__global__ void edge_agg256(const int* __restrict__ src, const int* __restrict__ dst,
                            const float* __restrict__ proj, const float* __restrict__ als,
                            const float* __restrict__ ald, const unsigned* __restrict__ mu,
                            float* __restrict__ acc, float* __restrict__ sden, int E) {
    int w = (blockIdx.x * blockDim.x + threadIdx.x) >> 5;
    int lane = threadIdx.x & 31;
    if (w >= E) return;
    int s = src[w], d = dst[w];
    float wt = 0.f;
    if (lane < 4) {
        float v = lrelu(als[s * 4 + lane] + ald[d * 4 + lane]);
        wt = __expf(v - decf(mu[d * 4 + lane]));
        atomicAdd(&sden[d * 4 + lane], wt);
    }
    float wh = __shfl_sync(0xffffffffu, wt, lane >> 3);
    const float4* ps = (const float4*)(proj + (size_t)s * 256);
    float* pa = acc + (size_t)d * 256;
    float4 p0 = ps[lane * 2];
    float4 p1 = ps[lane * 2 + 1];
    red4(pa + lane * 8,     wh * p0.x, wh * p0.y, wh * p0.z, wh * p0.w);
    red4(pa + lane * 8 + 4, wh * p1.x, wh * p1.y, wh * p1.z, wh * p1.w);
}

// HC=128, 1 head: each lane covers 4 channels
__global__ void edge_agg128(const int* __restrict__ src, const int* __restrict__ dst,
                            const float* __restrict__ proj, const float* __restrict__ als,
                            const float* __restrict__ ald, const unsigned* __restrict__ mu,
                            float* __restrict__ acc, float* __restrict__ sden, int E) {
    int w = (blockIdx.x * blockDim.x + threadIdx.x) >> 5;
    int lane = threadIdx.x & 31;
    if (w >= E) return;
    int s = src[w], d = dst[w];
    float wt = 0.f;
    if (lane == 0) {
        float v = lrelu(als[s] + ald[d]);
        wt = __expf(v - decf(mu[d]));
        atomicAdd(&sden[d], wt);
    }
    wt = __shfl_sync(0xffffffffu, wt, 0);
    float4 p = ((const float4*)(proj + (size_t)s * 128))[lane];
    red4(acc + (size_t)d * 128 + lane * 4, wt * p.x, wt * p.y, wt * p.z, wt * p.w);
}

// ---------------- finalize: divide + bias (+ optional residual / linear path) --------
__global__ void finalize_kernel(const float* __restrict__ acc, const float* __restrict__ sden,
                                const float* __restrict__ bias, const float* __restrict__ bias2,
                                const float* __restrict__ res, const float* __restrict__ lin,
                                float* __restrict__ out, int HCl, int Cshift, int H) {
    int idx = blockIdx.x * blockDim.x + threadIdx.x;
    int Q = HCl >> 2;
    if (idx >= NN * Q) return;
    int n = idx / Q;
    int c = (idx - n * Q) * 4;
    int h = c >> Cshift;
    float inv = 1.0f / sden[n * H + h];
    float4 a = *(const float4*)(acc + (size_t)n * HCl + c);
    float4 b = *(const float4*)(bias + c);
    float4 o = make_float4(a.x * inv + b.x, a.y * inv + b.y, a.z * inv + b.z, a.w * inv + b.w);
    if (bias2) {
        float4 b2 = *(const float4*)(bias2 + c);
        o.x += b2.x; o.y += b2.y; o.z += b2.z; o.w += b2.w;
    }
    if (res) {
        float4 r = *(const float4*)(res + (size_t)n * HCl + c);
        o.x += r.x; o.y += r.y; o.z += r.z; o.w += r.w;
    }
    if (lin) {
        float4 l = *(const float4*)(lin + (size_t)n * HCl + c);
        o.x += l.x; o.y += l.y; o.z += l.z; o.w += l.w;
    }
    *(float4*)(out + (size_t)n * HCl + c) = o;
}

// ---------------- host orchestration ----------------
extern "C" void kernel_launch(void* const* d_in, const int* in_sizes, int n_in,
                              void* d_out, int out_size) {
    const float* x   = (const float*)d_in[0];
    const void*  ei  = d_in[1];
    const float* W0  = (const float*)d_in[2];
    const float* as0 = (const float*)d_in[3];
    const float* ad0 = (const float*)d_in[4];
    const float* b0  = (const float*)d_in[5];
    const float* W1  = (const float*)d_in[6];
    const float* as1 = (const float*)d_in[7];
    const float* ad1 = (const float*)d_in[8];
    const float* b1  = (const float*)d_in[9];
    const float* W2  = (const float*)d_in[10];
    const float* as2 = (const float*)d_in[11];
    const float* ad2 = (const float*)d_in[12];
    const float* b2  = (const float*)d_in[13];
    const float* Wl  = (const float*)d_in[14];
    const float* bl  = (const float*)d_in[15];
    float* out = (float*)d_out;
    const int E = in_sizes[1] / 2;

    float *p_proj, *p_acc, *p_h0, *p_h1, *p_lin, *p_als, *p_ald, *p_sden;
    unsigned* p_mu;
    int *p_src, *p_dst;
    cudaGetSymbolAddress((void**)&p_proj, g_proj);
    cudaGetSymbolAddress((void**)&p_acc,  g_acc);
    cudaGetSymbolAddress((void**)&p_h0,   g_h0);
    cudaGetSymbolAddress((void**)&p_h1,   g_h1);
    cudaGetSymbolAddress((void**)&p_lin,  g_lin);
    cudaGetSymbolAddress((void**)&p_als,  g_als);
    cudaGetSymbolAddress((void**)&p_ald,  g_ald);
    cudaGetSymbolAddress((void**)&p_sden, g_sden);
    cudaGetSymbolAddress((void**)&p_mu,   g_mu);
    cudaGetSymbolAddress((void**)&p_src,  g_src);
    cudaGetSymbolAddress((void**)&p_dst,  g_dst);

    // normalize edge index dtype (int32 vs int64) into int32 scratch
    probe_kernel<<<1, 32>>>((const int*)ei, E > 1024 ? 1024 : E);
    convert_kernel<<<(E + 255) / 256, 256>>>(ei, E);

    auto run_layer = [&](const float* inp, const float* W, const float* a_s,
                         const float* a_d, const float* bias, int H, int C,
                         const float* res, const float* lin, const float* bias2,
                         float* outp) {
        const int HCl = H * C;
        const int Cshift = (C == 64) ? 6 : 7;
        gemm64<<<dim3(HCl / 64, (NN + 63) / 64), 256>>>(inp, W, p_proj, NN, 256, HCl);
        int warps = NN * H;
        if (H == 4)
            logits_kernel<4, 64><<<(warps * 32 + 255) / 256, 256>>>(p_proj, a_s, a_d, p_als, p_ald);
        else
            logits_kernel<1, 128><<<(warps * 32 + 255) / 256, 256>>>(p_proj, a_s, a_d, p_als, p_ald);
        self_init<<<(NN * H + 255) / 256, 256>>>(p_als, p_ald, p_mu, NN * H);
        if (H == 4)
            edge_max<4><<<(E + 255) / 256, 256>>>(p_src, p_dst, p_als, p_ald, p_mu, E);
        else
            edge_max<1><<<(E + 255) / 256, 256>>>(p_src, p_dst, p_als, p_ald, p_mu, E);
        int q = NN * HCl / 4;
        agg_init<<<(q + 255) / 256, 256>>>(p_proj, p_als, p_ald, p_mu, p_acc, p_sden, HCl, Cshift, H);
        long long tthreads = (long long)E * 32;
        int blocks = (int)((tthreads + 255) / 256);
        if (H == 4)
            edge_agg256<<<blocks, 256>>>(p_src, p_dst, p_proj, p_als, p_ald, p_mu, p_acc, p_sden, E);
        else
            edge_agg128<<<blocks, 256>>>(p_src, p_dst, p_proj, p_als, p_ald, p_mu, p_acc, p_sden, E);
        finalize_kernel<<<(q + 255) / 256, 256>>>(p_acc, p_sden, bias, bias2, res, lin, outp, HCl, Cshift, H);
    };

    // layer 0: x -> h0
    run_layer(x, W0, as0, ad0, b0, 4, 64, nullptr, nullptr, nullptr, p_h0);
    // layer 1: h0 -> h1 (residual h0)
    run_layer(p_h0, W1, as1, ad1, b1, 4, 64, p_h0, nullptr, nullptr, p_h1);
    // linear skip path: lin = h1 @ Wl
    gemm64<<<dim3(OUTC / 64, (NN + 63) / 64), 256>>>(p_h1, Wl, p_lin, NN, 256, OUTC);
    // layer 2: h1 -> out (1 head, 128 ch), + lin + bl
    run_layer(p_h1, W2, as2, ad2, b2, 1, 128, nullptr, p_lin, bl, out);
}

// round 3
// speedup vs baseline: 1.0001x; 1.0001x over previous
#include <cuda_runtime.h>

// ---------------- constants ----------------
#define NN      50000
#define MAXE    2000000
#define HEADS   4
#define HID     64
#define HC      256          // HEADS*HID
#define OUTC    128

// ---------------- device scratch ----------------
__device__ float    g_proj[(size_t)NN * HC];
__device__ float    g_acc [(size_t)NN * HC];
__device__ float    g_h0  [(size_t)NN * HC];
__device__ float    g_h1  [(size_t)NN * HC];
__device__ float    g_lin [(size_t)NN * OUTC];
__device__ float    g_als [NN * HEADS];
__device__ float    g_ald [NN * HEADS];
__device__ unsigned g_mu  [NN * HEADS];
__device__ float    g_sden[NN * HEADS];
__device__ int      g_src [MAXE];
__device__ int      g_dst [MAXE];
__device__ int      g_is64;

// ---------------- helpers ----------------
__device__ __forceinline__ unsigned encf(float f) {
    unsigned u = __float_as_uint(f);
    return (u & 0x80000000u) ? ~u : (u | 0x80000000u);
}
__device__ __forceinline__ float decf(unsigned u) {
    return (u & 0x80000000u) ? __uint_as_float(u & 0x7fffffffu)
                             : __uint_as_float(~u);
}
__device__ __forceinline__ float lrelu(float v) { return v > 0.f ? v : 0.2f * v; }

__device__ __forceinline__ void red4(float* addr, float a, float b, float c, float d) {
    asm volatile("red.global.add.v4.f32 [%0], {%1,%2,%3,%4};"
                 :: "l"(addr), "f"(a), "f"(b), "f"(c), "f"(d) : "memory");
}

// ---------------- edge index normalization ----------------
__global__ void probe_kernel(const int* p32, int nchk) {
    if (blockIdx.x == 0 && threadIdx.x == 0) {
        int z = 0;
        for (int k = 0; k < nchk; k++)
            if (p32[2 * k + 1] == 0) z++;
        g_is64 = (z * 2 > nchk) ? 1 : 0;
    }
}

__global__ void convert_kernel(const void* ei, int E) {
    int e = blockIdx.x * blockDim.x + threadIdx.x;
    if (e >= E || e >= MAXE) return;
    if (g_is64) {
        const long long* p = (const long long*)ei;
        g_src[e] = (int)p[e];
        g_dst[e] = (int)p[(size_t)E + e];
    } else {
        const int* p = (const int*)ei;
        g_src[e] = p[e];
        g_dst[e] = p[E + e];
    }
}

// ---------------- GEMM: C[M,N] = A[M,K] @ B[K,N], fp32, row-major ----------------
// BM=BN=64, BK=16, 256 threads, 4x4 register microtile
__global__ void gemm64(const float* __restrict__ A, const float* __restrict__ B,
                       float* __restrict__ C, int M, int K, int Nn) {
    __shared__ float As[16][68];
    __shared__ float Bs[16][68];
    const int tid = threadIdx.x;
    const int tx = tid & 15;
    const int ty = tid >> 4;
    const int rowBase = blockIdx.y * 64;
    const int colBase = blockIdx.x * 64;

    const int aRow = tid >> 2;           // 0..63
    const int aCol = (tid & 3) * 4;      // 0,4,8,12
    const int bRow = tid >> 4;           // 0..15
    const int bCol = (tid & 15) * 4;     // 0..60

    float acc[4][4];
#pragma unroll
    for (int i = 0; i < 4; i++)
#pragma unroll
        for (int j = 0; j < 4; j++) acc[i][j] = 0.f;

    for (int k0 = 0; k0 < K; k0 += 16) {
        float4 av = make_float4(0.f, 0.f, 0.f, 0.f);
        int gr = rowBase + aRow;
        if (gr < M) av = *(const float4*)(A + (size_t)gr * K + k0 + aCol);
        As[aCol + 0][aRow] = av.x;
        As[aCol + 1][aRow] = av.y;
        As[aCol + 2][aRow] = av.z;
        As[aCol + 3][aRow] = av.w;
        float4 bv = *(const float4*)(B + (size_t)(k0 + bRow) * Nn + colBase + bCol);
        *(float4*)&Bs[bRow][bCol] = bv;
        __syncthreads();
#pragma unroll
        for (int kk = 0; kk < 16; kk++) {
            float4 a4 = *(const float4*)&As[kk][ty * 4];
            float4 b4 = *(const float4*)&Bs[kk][tx * 4];
            float a[4] = {a4.x, a4.y, a4.z, a4.w};
            float b[4] = {b4.x, b4.y, b4.z, b4.w};
#pragma unroll
            for (int i = 0; i < 4; i++)
#pragma unroll
                for (int j = 0; j < 4; j++) acc[i][j] = fmaf(a[i], b[j], acc[i][j]);
        }
        __syncthreads();
    }
#pragma unroll
    for (int i = 0; i < 4; i++) {
        int r = rowBase + ty * 4 + i;
        if (r < M) {
            float4 v = make_float4(acc[i][0], acc[i][1], acc[i][2], acc[i][3]);
            *(float4*)(C + (size_t)r * Nn + colBase + tx * 4) = v;
        }
    }
}

// ---------------- per-node attention logits ----------------
template <int H, int C>
__global__ void logits_kernel(const float* __restrict__ proj,
                              const float* __restrict__ a_s,
                              const float* __restrict__ a_d,
                              float* __restrict__ als, float* __restrict__ ald) {
    int w = (blockIdx.x * blockDim.x + threadIdx.x) >> 5;
    int lane = threadIdx.x & 31;
    if (w >= NN * H) return;
    int n = w / H, h = w % H;
    const float* p = proj + (size_t)n * H * C + h * C;
    float ss = 0.f, sd = 0.f;
#pragma unroll
    for (int c = lane; c < C; c += 32) {
        float v = p[c];
        ss = fmaf(v, a_s[h * C + c], ss);
        sd = fmaf(v, a_d[h * C + c], sd);
    }
#pragma unroll
    for (int o = 16; o > 0; o >>= 1) {
        ss += __shfl_xor_sync(0xffffffffu, ss, o);
        sd += __shfl_xor_sync(0xffffffffu, sd, o);
    }
    if (lane == 0) {
        als[n * H + h] = ss;
        ald[n * H + h] = sd;
    }
}

// ---------------- self-loop init of max ----------------
__global__ void self_init(const float* __restrict__ als, const float* __restrict__ ald,
                          unsigned* __restrict__ mu, int total) {
    int i = blockIdx.x * blockDim.x + threadIdx.x;
    if (i >= total) return;
    mu[i] = encf(lrelu(als[i] + ald[i]));
}

// ---------------- edge max pass ----------------
template <int H>
__global__ void edge_max(const int* __restrict__ src, const int* __restrict__ dst,
                         const float* __restrict__ als, const float* __restrict__ ald,
                         unsigned* __restrict__ mu, int E) {
    int e = blockIdx.x * blockDim.x + threadIdx.x;
    if (e >= E) return;
    int s = src[e], d = dst[e];
#pragma unroll
    for (int h = 0; h < H; h++) {
        float v = lrelu(als[s * H + h] + ald[d * H + h]);
        atomicMax(&mu[d * H + h], encf(v));
    }
}

// ---------------- self-loop init of accumulators ----------------
__global__ void agg_init(const float* __restrict__ proj, const float* __restrict__ als,
                         const float* __restrict__ ald, const unsigned* __restrict__ mu,
                         float* __restrict__ acc, float* __restrict__ sden,
                         int HCl, int Cshift, int H) {
    int idx = blockIdx.x * blockDim.x + threadIdx.x;
    int Q = HCl >> 2;
    if (idx >= NN * Q) return;
    int n = idx / Q;
    int c = (idx - n * Q) * 4;
    int h = c >> Cshift;
    float v = lrelu(als[n * H + h] + ald[n * H + h]);
    float w = __expf(v - decf(mu[n * H + h]));
    if ((c & ((1 << Cshift) - 1)) == 0) sden[n * H + h] = w;
    float4 p = *(const float4*)(proj + (size_t)n * HCl + c);
    float4 o = make_float4(w * p.x, w * p.y, w * p.z, w * p.w);
    *(float4*)(acc + (size_t)n * HCl + c) = o;
}

// ---------------- edge aggregation: warp per edge ----------------
// HC=256 (4 heads x 64): each lane covers 8 channels (2 x float4)
__global__ void edge_agg256(const int* __restrict__ src, const int* __restrict__ dst,
                            const float* __restrict__ proj, const float* __restrict__ als,
                            const float* __restrict__ ald, const unsigned* __restrict__ mu,
                            float* __restrict__ acc, float* __restrict__ sden, int E) {
    int w = (blockIdx.x * blockDim.x + threadIdx.x) >> 5;
    int lane = threadIdx.x & 31;
    if (w >= E) return;
    int s = src[w], d = dst[w];
    float wt = 0.f;
    if (lane < 4) {
        float v = lrelu(als[s * 4 + lane] + ald[d * 4 + lane]);
        wt = __expf(v - decf(mu[d * 4 + lane]));
        atomicAdd(&sden[d * 4 + lane], wt);
    }
    float wh = __shfl_sync(0xffffffffu, wt, lane >> 3);
    const float4* ps = (const float4*)(proj + (size_t)s * 256);
    float* pa = acc + (size_t)d * 256;
    float4 p0 = ps[lane * 2];
    float4 p1 = ps[lane * 2 + 1];
    red4(pa + lane * 8,     wh * p0.x, wh * p0.y, wh * p0.z, wh * p0.w);
    red4(pa + lane * 8 + 4, wh * p1.x, wh * p1.y, wh * p1.z, wh * p1.w);
}

// HC=128, 1 head: each lane covers 4 channels
__global__ void edge_agg128(const int* __restrict__ src, const int* __restrict__ dst,
                            const float* __restrict__ proj, const float* __restrict__ als,
                            const float* __restrict__ ald, const unsigned* __restrict__ mu,
                            float* __restrict__ acc, float* __restrict__ sden, int E) {
    int w = (blockIdx.x * blockDim.x + threadIdx.x) >> 5;
    int lane = threadIdx.x & 31;
    if (w >= E) return;
    int s = src[w], d = dst[w];
    float wt = 0.f;
    if (lane == 0) {
        float v = lrelu(als[s] + ald[d]);
        wt = __expf(v - decf(mu[d]));
        atomicAdd(&sden[d], wt);
    }
    wt = __shfl_sync(0xffffffffu, wt, 0);
    float4 p = ((const float4*)(proj + (size_t)s * 128))[lane];
    red4(acc + (size_t)d * 128 + lane * 4, wt * p.x, wt * p.y, wt * p.z, wt * p.w);
}

// ---------------- finalize: divide + bias (+ optional residual / linear path) --------
__global__ void finalize_kernel(const float* __restrict__ acc, const float* __restrict__ sden,
                                const float* __restrict__ bias, const float* __restrict__ bias2,
                                const float* __restrict__ res, const float* __restrict__ lin,
                                float* __restrict__ out, int HCl, int Cshift, int H) {
    int idx = blockIdx.x * blockDim.x + threadIdx.x;
    int Q = HCl >> 2;
    if (idx >= NN * Q) return;
    int n = idx / Q;
    int c = (idx - n * Q) * 4;
    int h = c >> Cshift;
    float inv = 1.0f / sden[n * H + h];
    float4 a = *(const float4*)(acc + (size_t)n * HCl + c);
    float4 b = *(const float4*)(bias + c);
    float4 o = make_float4(a.x * inv + b.x, a.y * inv + b.y, a.z * inv + b.z, a.w * inv + b.w);
    if (bias2) {
        float4 b2 = *(const float4*)(bias2 + c);
        o.x += b2.x; o.y += b2.y; o.z += b2.z; o.w += b2.w;
    }
    if (res) {
        float4 r = *(const float4*)(res + (size_t)n * HCl + c);
        o.x += r.x; o.y += r.y; o.z += r.z; o.w += r.w;
    }
    if (lin) {
        float4 l = *(const float4*)(lin + (size_t)n * HCl + c);
        o.x += l.x; o.y += l.y; o.z += l.z; o.w += l.w;
    }
    *(float4*)(out + (size_t)n * HCl + c) = o;
}

// ---------------- host orchestration ----------------
extern "C" void kernel_launch(void* const* d_in, const int* in_sizes, int n_in,
                              void* d_out, int out_size) {
    const float* x   = (const float*)d_in[0];
    const void*  ei  = d_in[1];
    const float* W0  = (const float*)d_in[2];
    const float* as0 = (const float*)d_in[3];
    const float* ad0 = (const float*)d_in[4];
    const float* b0  = (const float*)d_in[5];
    const float* W1  = (const float*)d_in[6];
    const float* as1 = (const float*)d_in[7];
    const float* ad1 = (const float*)d_in[8];
    const float* b1  = (const float*)d_in[9];
    const float* W2  = (const float*)d_in[10];
    const float* as2 = (const float*)d_in[11];
    const float* ad2 = (const float*)d_in[12];
    const float* b2  = (const float*)d_in[13];
    const float* Wl  = (const float*)d_in[14];
    const float* bl  = (const float*)d_in[15];
    float* out = (float*)d_out;
    const int E = in_sizes[1] / 2;

    float *p_proj, *p_acc, *p_h0, *p_h1, *p_lin, *p_als, *p_ald, *p_sden;
    unsigned* p_mu;
    int *p_src, *p_dst;
    cudaGetSymbolAddress((void**)&p_proj, g_proj);
    cudaGetSymbolAddress((void**)&p_acc,  g_acc);
    cudaGetSymbolAddress((void**)&p_h0,   g_h0);
    cudaGetSymbolAddress((void**)&p_h1,   g_h1);
    cudaGetSymbolAddress((void**)&p_lin,  g_lin);
    cudaGetSymbolAddress((void**)&p_als,  g_als);
    cudaGetSymbolAddress((void**)&p_ald,  g_ald);
    cudaGetSymbolAddress((void**)&p_sden, g_sden);
    cudaGetSymbolAddress((void**)&p_mu,   g_mu);
    cudaGetSymbolAddress((void**)&p_src,  g_src);
    cudaGetSymbolAddress((void**)&p_dst,  g_dst);

    // normalize edge index dtype (int32 vs int64) into int32 scratch
    probe_kernel<<<1, 32>>>((const int*)ei, E > 1024 ? 1024 : E);
    convert_kernel<<<(E + 255) / 256, 256>>>(ei, E);

    auto run_layer = [&](const float* inp, const float* W, const float* a_s,
                         const float* a_d, const float* bias, int H, int C,
                         const float* res, const float* lin, const float* bias2,
                         float* outp) {
        const int HCl = H * C;
        const int Cshift = (C == 64) ? 6 : 7;
        gemm64<<<dim3(HCl / 64, (NN + 63) / 64), 256>>>(inp, W, p_proj, NN, 256, HCl);
        int warps = NN * H;
        if (H == 4)
            logits_kernel<4, 64><<<(warps * 32 + 255) / 256, 256>>>(p_proj, a_s, a_d, p_als, p_ald);
        else
            logits_kernel<1, 128><<<(warps * 32 + 255) / 256, 256>>>(p_proj, a_s, a_d, p_als, p_ald);
        self_init<<<(NN * H + 255) / 256, 256>>>(p_als, p_ald, p_mu, NN * H);
        if (H == 4)
            edge_max<4><<<(E + 255) / 256, 256>>>(p_src, p_dst, p_als, p_ald, p_mu, E);
        else
            edge_max<1><<<(E + 255) / 256, 256>>>(p_src, p_dst, p_als, p_ald, p_mu, E);
        int q = NN * HCl / 4;
        agg_init<<<(q + 255) / 256, 256>>>(p_proj, p_als, p_ald, p_mu, p_acc, p_sden, HCl, Cshift, H);
        long long tthreads = (long long)E * 32;
        int blocks = (int)((tthreads + 255) / 256);
        if (H == 4)
            edge_agg256<<<blocks, 256>>>(p_src, p_dst, p_proj, p_als, p_ald, p_mu, p_acc, p_sden, E);
        else
            edge_agg128<<<blocks, 256>>>(p_src, p_dst, p_proj, p_als, p_ald, p_mu, p_acc, p_sden, E);
        finalize_kernel<<<(q + 255) / 256, 256>>>(p_acc, p_sden, bias, bias2, res, lin, outp, HCl, Cshift, H);
    };

    // layer 0: x -> h0
    run_layer(x, W0, as0, ad0, b0, 4, 64, nullptr, nullptr, nullptr, p_h0);
    // layer 1: h0 -> h1 (residual h0)
    run_layer(p_h0, W1, as1, ad1, b1, 4, 64, p_h0, nullptr, nullptr, p_h1);
    // linear skip path: lin = h1 @ Wl
    gemm64<<<dim3(OUTC / 64, (NN + 63) / 64), 256>>>(p_h1, Wl, p_lin, NN, 256, OUTC);
    // layer 2: h1 -> out (1 head, 128 ch), + lin + bl
    run_layer(p_h1, W2, as2, ad2, b2, 1, 128, nullptr, p_lin, bl, out);
}